// round 7
// baseline (speedup 1.0000x reference)
#include <cuda_runtime.h>
#include <stdint.h>

#define NUM_HEADS 12
#define HEAD_DIM  64
#define HIDDEN    768
#define BATCH     2
#define SEQ       2048
#define M_TOTAL   (BATCH*SEQ)   // 4096
#define LOG2E     1.44269504f

// Scratch: Q,K in [B,H,S,d] with d permuted within 16-groups (see pos16);
// V stored TRANSPOSED [B,H,d,S] with key permuted within 16-groups.
// All pre-rounded to tf32; Q pre-scaled by 0.125*log2(e).
__device__ float g_qkv[3][BATCH*NUM_HEADS*SEQ*HEAD_DIM];

__device__ __forceinline__ uint32_t f2tf32(float f) {
    uint32_t u;
    asm("cvt.rna.tf32.f32 %0, %1;" : "=r"(u) : "f"(f));
    return u;
}

__device__ __forceinline__ float ex2(float f) {
    float r;
    asm("ex2.approx.f32 %0, %1;" : "=f"(r) : "f"(f));
    return r;
}

__device__ __forceinline__ void mma_tf32(float c[4], const uint32_t a[4],
                                         uint32_t b0, uint32_t b1) {
    asm volatile(
        "mma.sync.aligned.m16n8k8.row.col.f32.tf32.tf32.f32 "
        "{%0,%1,%2,%3}, {%4,%5,%6,%7}, {%8,%9}, {%0,%1,%2,%3};"
        : "+f"(c[0]), "+f"(c[1]), "+f"(c[2]), "+f"(c[3])
        : "r"(a[0]), "r"(a[1]), "r"(a[2]), "r"(a[3]), "r"(b0), "r"(b1));
}

__device__ __forceinline__ void ldsm_x4(uint32_t r[4], uint32_t addr) {
    asm volatile("ldmatrix.sync.aligned.m8n8.x4.shared.b16 {%0,%1,%2,%3}, [%4];"
        : "=r"(r[0]), "=r"(r[1]), "=r"(r[2]), "=r"(r[3]) : "r"(addr));
}

__device__ __forceinline__ void sts_v2(uint32_t addr, float a, float b) {
    asm volatile("st.shared.v2.f32 [%0], {%1,%2};" :: "r"(addr), "f"(a), "f"(b));
}

__device__ __forceinline__ void cpasync16(uint32_t dst, const void* src) {
    asm volatile("cp.async.cg.shared.global [%0], [%1], 16;" :: "r"(dst), "l"(src));
}
#define CP_COMMIT() asm volatile("cp.async.commit_group;")
#define CP_WAIT1()  asm volatile("cp.async.wait_group 1;")
#define CP_WAIT2()  asm volatile("cp.async.wait_group 2;")

// physical position of logical index r within its 16-group
__device__ __forceinline__ int pos16(int r) {
    return 4 * (r & 3) + 2 * (r >> 3) + ((r >> 2) & 1);
}
__device__ __forceinline__ int perm16(int d) {
    return (d & ~15) | pos16(d & 15);
}

// ---------------------------------------------------------------------------
// QKV projection, tf32 tensor cores, register-prefetch double buffering.
// BM=128, BN=64, BK=32. 256 threads, 8 warps = 4(m) x 2(n).
// Epilogue writes the permuted layouts described above.
// ---------------------------------------------------------------------------
__global__ __launch_bounds__(256, 2) void qkv_proj_kernel(
    const float* __restrict__ x,
    const float* __restrict__ Wq, const float* __restrict__ bq,
    const float* __restrict__ Wk, const float* __restrict__ bk,
    const float* __restrict__ Wv, const float* __restrict__ bv)
{
    const int z = blockIdx.z;
    const float* Wp   = (z == 0) ? Wq : (z == 1) ? Wk : Wv;
    const float* bias = (z == 0) ? bq : (z == 1) ? bk : bv;

    __shared__ uint32_t Xs[128 * 36];   // [m][k], stride 36
    __shared__ uint32_t Ws[32 * 72];    // [k][n], stride 72

    const int tid  = threadIdx.x;
    const int lane = tid & 31;
    const int warp = tid >> 5;
    const int wm = warp >> 1;
    const int wn = warp & 1;
    const int m0 = blockIdx.x * 128;
    const int n0 = blockIdx.y * 64;
    const int r0 = lane >> 2;
    const int q2 = lane & 3;

    const int xr_r = tid >> 3, xr_c = (tid & 7) * 4;
    const int wr_r = tid >> 4, wr_c = (tid & 15) * 4;

    float4 xr[4], wr[2];
    #pragma unroll
    for (int it = 0; it < 4; ++it)
        xr[it] = *(const float4*)(x + (size_t)(m0 + xr_r + it * 32) * HIDDEN + xr_c);
    #pragma unroll
    for (int it = 0; it < 2; ++it)
        wr[it] = *(const float4*)(Wp + (size_t)(wr_r + it * 16) * HIDDEN + n0 + wr_c);

    float acc[2][4][4] = {};

    for (int k0 = 0; k0 < HIDDEN; k0 += 32) {
        #pragma unroll
        for (int it = 0; it < 4; ++it) {
            uint4 u = { f2tf32(xr[it].x), f2tf32(xr[it].y), f2tf32(xr[it].z), f2tf32(xr[it].w) };
            *(uint4*)&Xs[(xr_r + it * 32) * 36 + xr_c] = u;
        }
        #pragma unroll
        for (int it = 0; it < 2; ++it) {
            uint4 u = { f2tf32(wr[it].x), f2tf32(wr[it].y), f2tf32(wr[it].z), f2tf32(wr[it].w) };
            *(uint4*)&Ws[(wr_r + it * 16) * 72 + wr_c] = u;
        }
        __syncthreads();

        if (k0 + 32 < HIDDEN) {
            #pragma unroll
            for (int it = 0; it < 4; ++it)
                xr[it] = *(const float4*)(x + (size_t)(m0 + xr_r + it * 32) * HIDDEN + k0 + 32 + xr_c);
            #pragma unroll
            for (int it = 0; it < 2; ++it)
                wr[it] = *(const float4*)(Wp + (size_t)(k0 + 32 + wr_r + it * 16) * HIDDEN + n0 + wr_c);
        }

        #pragma unroll
        for (int ks = 0; ks < 4; ++ks) {
            uint32_t a[2][4];
            #pragma unroll
            for (int mt = 0; mt < 2; ++mt) {
                int R = wm * 32 + mt * 16 + r0;
                int C = ks * 8 + q2;
                a[mt][0] = Xs[R * 36 + C];
                a[mt][1] = Xs[(R + 8) * 36 + C];
                a[mt][2] = Xs[R * 36 + C + 4];
                a[mt][3] = Xs[(R + 8) * 36 + C + 4];
            }
            #pragma unroll
            for (int nt = 0; nt < 4; ++nt) {
                int Kr = ks * 8 + q2;
                int Cn = wn * 32 + nt * 8 + r0;
                uint32_t b0 = Ws[Kr * 72 + Cn];
                uint32_t b1 = Ws[(Kr + 4) * 72 + Cn];
                mma_tf32(acc[0][nt], a[0], b0, b1);
                mma_tf32(acc[1][nt], a[1], b0, b1);
            }
        }
        __syncthreads();
    }

    const int h = blockIdx.y;
    if (z != 2) {
        float* out = g_qkv[z];
        const float scale = (z == 0) ? 0.125f * LOG2E : 1.0f;
        #pragma unroll
        for (int mt = 0; mt < 2; ++mt)
            #pragma unroll
            for (int nt = 0; nt < 4; ++nt) {
                int dcol = wn * 32 + nt * 8 + 2 * q2;
                int d0 = perm16(dcol);
                int d1 = perm16(dcol + 1);
                float b0 = bias[n0 + dcol];
                float b1 = bias[n0 + dcol + 1];
                #pragma unroll
                for (int half = 0; half < 2; ++half) {
                    int m  = m0 + wm * 32 + mt * 16 + r0 + half * 8;
                    int bI = m >> 11;
                    int sI = m & 2047;
                    float* po = out + (((size_t)(bI * NUM_HEADS + h)) * SEQ + sI) * HEAD_DIM;
                    po[d0] = __uint_as_float(f2tf32((acc[mt][nt][half * 2 + 0] + b0) * scale));
                    po[d1] = __uint_as_float(f2tf32((acc[mt][nt][half * 2 + 1] + b1) * scale));
                }
            }
    } else {
        // V: transposed store [B,H,d,S], key index permuted within 16-groups
        float* outT = g_qkv[2];
        #pragma unroll
        for (int mt = 0; mt < 2; ++mt)
            #pragma unroll
            for (int nt = 0; nt < 4; ++nt) {
                int dcol = wn * 32 + nt * 8 + 2 * q2;
                float b0 = bias[n0 + dcol];
                float b1 = bias[n0 + dcol + 1];
                #pragma unroll
                for (int half = 0; half < 2; ++half) {
                    int m  = m0 + wm * 32 + mt * 16 + r0 + half * 8;
                    int bI = m >> 11;
                    int sI = m & 2047;
                    int sp = (sI & ~15) | pos16(sI & 15);
                    size_t base = (size_t)(bI * NUM_HEADS + h) * 64;
                    outT[(base + dcol) * SEQ + sp] =
                        __uint_as_float(f2tf32(acc[mt][nt][half * 2 + 0] + b0));
                    outT[(base + dcol + 1) * SEQ + sp] =
                        __uint_as_float(f2tf32(acc[mt][nt][half * 2 + 1] + b1));
                }
            }
    }
}

// ---------------------------------------------------------------------------
// Flash attention, tf32, cp.async pipelined. Br=64 (4 warps), Bc=64.
// K double-buffered (stride 80 -> conflict-free LDS.128 fragment loads via
// the 16-group permutation), V single-buffered. P transposed via STS into
// the dead K(t) buffer + ldmatrix.b16 (no cvt: tensor HW truncates f32).
// smem: 3 * 64*80 words = 61440 B -> 3 CTAs/SM.
// ---------------------------------------------------------------------------
#define KTILE  5120    // 64*80 words
#define KTILEB 20480   // bytes

__global__ __launch_bounds__(128, 3) void attn_kernel(
    const float* __restrict__ mask,   // [B,1,1,S]
    float* __restrict__ out)          // [B,S,HIDDEN]
{
    extern __shared__ __align__(16) uint32_t sm[];
    // layout: K0 | K1 | V, each KTILE words

    const int tid  = threadIdx.x;
    const int lane = tid & 31;
    const int warp = tid >> 5;
    const int r0 = lane >> 2;
    const int q2 = lane & 3;
    const int qbase = blockIdx.x * 64;
    const int bh = blockIdx.y;
    const int b  = bh / NUM_HEADS;
    const int h  = bh - b * NUM_HEADS;

    const float* Qg = g_qkv[0] + (size_t)bh * SEQ * 64;
    const float* Kg = g_qkv[1] + (size_t)bh * SEQ * 64;
    const float* Vg = g_qkv[2] + (size_t)bh * 64 * SEQ;   // [d][S]
    const float2* mrow2base = (const float2*)(mask + (size_t)b * SEQ);

    const int rowk = tid >> 4;          // 0..7
    const int ch4  = (tid & 15) * 4;    // 0..60
    const uint32_t sbase = (uint32_t)__cvta_generic_to_shared(sm);
    const uint32_t kdst0 = sbase + (uint32_t)(rowk * 80 + ch4) * 4;
    const uint32_t vdst  = sbase + (uint32_t)(2 * KTILE + rowk * 80 + ch4) * 4;
    const float* ksrc0 = Kg + rowk * 64 + ch4;
    const float* vsrc0 = Vg + rowk * 2048 + ch4;

    // prologue commits (order matters for wait_group math): [K0] [V0] [K1]
    #pragma unroll
    for (int i = 0; i < 8; ++i)
        cpasync16(kdst0 + i * (8 * 80 * 4), ksrc0 + i * 512);
    CP_COMMIT();
    #pragma unroll
    for (int i = 0; i < 8; ++i)
        cpasync16(vdst + i * (8 * 80 * 4), vsrc0 + i * 16384);
    CP_COMMIT();
    #pragma unroll
    for (int i = 0; i < 8; ++i)
        cpasync16(kdst0 + KTILEB + i * (8 * 80 * 4), ksrc0 + 4096 + i * 512);
    CP_COMMIT();

    // Q fragments: permuted gmem layout makes each float4 = (a0,a2) of two ksteps
    uint32_t Qa[8][4];
    {
        const float* qp = Qg + (size_t)(qbase + warp * 16 + r0) * 64;
        #pragma unroll
        for (int g = 0; g < 4; ++g) {
            float4 lo = *(const float4*)(qp + g * 16 + q2 * 4);
            float4 hi = *(const float4*)(qp + 512 + g * 16 + q2 * 4);
            Qa[2*g][0]   = __float_as_uint(lo.x);
            Qa[2*g][2]   = __float_as_uint(lo.y);
            Qa[2*g+1][0] = __float_as_uint(lo.z);
            Qa[2*g+1][2] = __float_as_uint(lo.w);
            Qa[2*g][1]   = __float_as_uint(hi.x);
            Qa[2*g][3]   = __float_as_uint(hi.y);
            Qa[2*g+1][1] = __float_as_uint(hi.z);
            Qa[2*g+1][3] = __float_as_uint(hi.w);
        }
    }

    float accO[8][4] = {};
    float lr0 = 0.0f, lr1 = 0.0f;

    // ldmatrix per-lane address components (P region, row stride 72 words)
    const int lrow = (lane & 7) | ((lane >> 1) & 8);
    const int lcb  = (lane >> 3) & 1;

    for (int t = 0; t < 32; ++t) {
        CP_WAIT2();             // K(t) guaranteed done; V(t), K(t+1) may pend
        __syncthreads();

        // S = Q K^T  (LDS.128 -> fragments for two ksteps at once)
        const uint32_t* Kb = sm + (t & 1) * KTILE;
        float s[8][4] = {};
        #pragma unroll
        for (int g = 0; g < 4; ++g)
            #pragma unroll
            for (int nt = 0; nt < 8; ++nt) {
                uint4 u = *(const uint4*)&Kb[(nt * 8 + r0) * 80 + g * 16 + q2 * 4];
                mma_tf32(s[nt], Qa[2*g],   u.x, u.y);
                mma_tf32(s[nt], Qa[2*g+1], u.z, u.w);
            }

        // mask (x log2e) + exp2 + row sums
        const float2* mrow2 = mrow2base + t * 32;
        float sum0 = 0.0f, sum1 = 0.0f;
        #pragma unroll
        for (int nt = 0; nt < 8; ++nt) {
            float2 mv = mrow2[nt * 4 + q2];
            float mx = mv.x * LOG2E, my = mv.y * LOG2E;
            s[nt][0] = ex2(s[nt][0] + mx);
            s[nt][1] = ex2(s[nt][1] + my);
            s[nt][2] = ex2(s[nt][2] + mx);
            s[nt][3] = ex2(s[nt][3] + my);
            sum0 += s[nt][0] + s[nt][1];
            sum1 += s[nt][2] + s[nt][3];
        }
        sum0 += __shfl_xor_sync(0xffffffffu, sum0, 1);
        sum0 += __shfl_xor_sync(0xffffffffu, sum0, 2);
        sum1 += __shfl_xor_sync(0xffffffffu, sum1, 1);
        sum1 += __shfl_xor_sync(0xffffffffu, sum1, 2);
        lr0 += sum0;
        lr1 += sum1;

        CP_WAIT1();             // V(t) guaranteed done; K(t+1) may pend
        __syncthreads();        // all QK reads of K(t) done; V visible

        // P -> smem (dead K(t) buffer, warp-private slice, stride 72 words)
        const uint32_t Pb = sbase + (uint32_t)(t & 1) * KTILEB + (uint32_t)warp * 5120;
        {
            uint32_t a0 = Pb + (uint32_t)(r0 * 288 + q2 * 8);
            uint32_t a1 = a0 + 8 * 288;
            #pragma unroll
            for (int nt = 0; nt < 8; ++nt) {
                sts_v2(a0 + nt * 32, s[nt][0], s[nt][1]);
                sts_v2(a1 + nt * 32, s[nt][2], s[nt][3]);
            }
        }
        __syncwarp();

        // O += P @ V  (ldmatrix rebuilds A-frags; V via LDS.128 pairs)
        const uint32_t* Vb = sm + 2 * KTILE;
        const uint32_t lm_base = Pb + (uint32_t)(lrow * 288 + lcb * 16);
        #pragma unroll
        for (int g = 0; g < 4; ++g) {
            uint32_t R[4], aLo[4], aHi[4];
            ldsm_x4(R, lm_base + (2 * g) * 32);
            aLo[0] = R[0]; aLo[1] = R[2]; aLo[2] = R[1]; aLo[3] = R[3];
            ldsm_x4(R, lm_base + (2 * g + 1) * 32);
            aHi[0] = R[0]; aHi[1] = R[2]; aHi[2] = R[1]; aHi[3] = R[3];
            #pragma unroll
            for (int nt = 0; nt < 8; ++nt) {
                uint4 v = *(const uint4*)&Vb[(nt * 8 + r0) * 80 + g * 16 + q2 * 4];
                mma_tf32(accO[nt], aLo, v.x, v.y);
                mma_tf32(accO[nt], aHi, v.z, v.w);
            }
        }

        __syncthreads();        // PV done (V reusable), LDSM done (K(t) buf reusable)
        {
            // commit order per tile: [V(t+1)] then [K(t+2)]
            int tv = (t + 1) & 31;
            const float* vs = vsrc0 + tv * 64;
            #pragma unroll
            for (int i = 0; i < 8; ++i)
                cpasync16(vdst + i * (8 * 80 * 4), vs + i * 16384);
            CP_COMMIT();
            int tk = (t + 2) & 31;
            const float* ks = ksrc0 + tk * 4096;
            uint32_t kd = kdst0 + (uint32_t)(t & 1) * KTILEB;
            #pragma unroll
            for (int i = 0; i < 8; ++i)
                cpasync16(kd + i * (8 * 80 * 4), ks + i * 512);
            CP_COMMIT();
        }
    }

    // Finalize: divide by row sums, write [B,S,HIDDEN]
    float inv0 = 1.0f / lr0;
    float inv1 = 1.0f / lr1;
    int row = qbase + warp * 16 + r0;
    #pragma unroll
    for (int nt = 0; nt < 8; ++nt) {
        int dcol = nt * 8 + 2 * q2;
        float2 o0 = { accO[nt][0] * inv0, accO[nt][1] * inv0 };
        *(float2*)(out + ((size_t)(b * SEQ + row)) * HIDDEN + h * 64 + dcol) = o0;
        float2 o1 = { accO[nt][2] * inv1, accO[nt][3] * inv1 };
        *(float2*)(out + ((size_t)(b * SEQ + row + 8)) * HIDDEN + h * 64 + dcol) = o1;
    }
}

extern "C" void kernel_launch(void* const* d_in, const int* in_sizes, int n_in,
                              void* d_out, int out_size) {
    const float* x   = (const float*)d_in[0];
    const float* msk = (const float*)d_in[1];
    const float* Wq  = (const float*)d_in[2];
    const float* bq  = (const float*)d_in[3];
    const float* Wk  = (const float*)d_in[4];
    const float* bk  = (const float*)d_in[5];
    const float* Wv  = (const float*)d_in[6];
    const float* bv  = (const float*)d_in[7];
    float* out = (float*)d_out;

    cudaFuncSetAttribute(attn_kernel, cudaFuncAttributeMaxDynamicSharedMemorySize,
                         3 * KTILEB);

    qkv_proj_kernel<<<dim3(M_TOTAL / 128, HIDDEN / 64, 3), 256>>>(x, Wq, bq, Wk, bk, Wv, bv);
    attn_kernel<<<dim3(SEQ / 64, BATCH * NUM_HEADS), 128, 3 * KTILEB>>>(msk, out);
}